// round 1
// baseline (speedup 1.0000x reference)
#include <cuda_runtime.h>
#include <math.h>

// ---------------------------------------------------------------------------
// QAttention: fused quaternion-conv channel-attention.
// Pipeline:
//   P0 expand Hamilton blocks -> full weights (qkv 384x128, dw 384x384x9, po 128x128)
//   P1 Weff[o][c][tap] = sum_m Wdw[o][m][tap] * Wqkv[m][c]  (fold 1x1 into 3x3)
//      t[o][tap]       = sum_m Wdw[o][m][tap] * qkv_b[m]    (bias-through-conv term)
//   P2 fused 3x3 conv: qkv2 = Weff (*) x  + per-tap-valid bias  (implicit GEMM, fp32)
//   P3 L2 norms of q,k rows (inverse norms)
//   P4 attn logits 32x32 per (b,h) with K-split + atomics
//   P5 softmax (with inv-norm + temperature scaling fused)
//   P6 out = attn @ v
//   P7 po 1x1 conv (SGEMM) + bias -> d_out
// ---------------------------------------------------------------------------

#define IMGN 128
#define SPATIAL 16384

// scratch (device globals; no allocation allowed)
__device__ float g_Wqkv[384 * 128];
__device__ float g_Wdw[384 * 384 * 9];
__device__ float g_Wpo[128 * 128];
__device__ float g_Weff[384 * 128 * 9];
__device__ float g_tb[384 * 9];
__device__ float g_qkv2[2 * 384 * SPATIAL];   // 50.3 MB
__device__ float g_av[2 * 128 * SPATIAL];     // 16.8 MB
__device__ float g_attnP[2 * 4 * 32 * 32];
__device__ float g_attn[2 * 4 * 32 * 32];
__device__ float g_inv[2 * 2 * 128];          // [qk][b][ch]

// ---------------------------------------------------------------------------
// P0: Hamilton-product block expansion.
// W[(br*O4+oo)][(bc*C4+cc)][tap] = sgn[br][bc] * comp(src[br][bc])[oo][cc][tap]
// ---------------------------------------------------------------------------
__global__ void expand_hamilton(const float* __restrict__ r,
                                const float* __restrict__ i_,
                                const float* __restrict__ j_,
                                const float* __restrict__ k_,
                                int dest, int O4, int C4, int T) {
    int idx = blockIdx.x * blockDim.x + threadIdx.x;
    int total = 16 * O4 * C4 * T;
    if (idx >= total) return;

    int tap = idx % T;
    int rem = idx / T;
    int C = 4 * C4;
    int c = rem % C;
    int o = rem / C;
    int br = o / O4, oo = o % O4;
    int bc = c / C4, cc = c % C4;

    const int   src[16] = {0,1,2,3, 1,0,3,2, 2,3,0,1, 3,2,1,0};
    const float sgn[16] = {1.f,-1.f,-1.f,-1.f, 1.f,1.f,-1.f,1.f,
                           1.f,1.f,1.f,-1.f,  1.f,-1.f,1.f,1.f};
    const float* comp[4] = {r, i_, j_, k_};

    float v = sgn[br * 4 + bc] * comp[src[br * 4 + bc]][(oo * C4 + cc) * T + tap];
    float* out = (dest == 0) ? g_Wqkv : (dest == 1) ? g_Wdw : g_Wpo;
    out[idx] = v;
}

// ---------------------------------------------------------------------------
// P1: Weff and per-tap bias t. One block per (o, tap); 128 threads = c.
// ---------------------------------------------------------------------------
__global__ void make_weff(const float* __restrict__ qkv_b) {
    int o   = blockIdx.x / 9;
    int tap = blockIdx.x % 9;
    int tid = threadIdx.x;

    __shared__ float wrow[384];
    __shared__ float red[128];

    for (int m = tid; m < 384; m += 128)
        wrow[m] = g_Wdw[(o * 384 + m) * 9 + tap];
    __syncthreads();

    float acc = 0.f;
    for (int m = 0; m < 384; ++m)
        acc = fmaf(wrow[m], g_Wqkv[m * 128 + tid], acc);
    g_Weff[o * 1152 + tid * 9 + tap] = acc;

    float tb = 0.f;
    for (int m = tid; m < 384; m += 128)
        tb = fmaf(wrow[m], qkv_b[m], tb);
    red[tid] = tb;
    __syncthreads();
    for (int s = 64; s > 0; s >>= 1) {
        if (tid < s) red[tid] += red[tid + s];
        __syncthreads();
    }
    if (tid == 0) g_tb[o * 9 + tap] = red[0];
}

// ---------------------------------------------------------------------------
// P2: fused 3x3 conv as implicit GEMM.
// Block: one image row y (128 pixels), 128 outputs (M-tile), one batch.
// 256 threads, 8x8 micro-tile. K loop: 32 chunks of 4 channels x 9 taps.
// Bs holds raw input rows with zeroed halo -> dx shift is a smem offset.
// ---------------------------------------------------------------------------
__global__ __launch_bounds__(256, 2)
void conv_fused(const float* __restrict__ X, const float* __restrict__ dwb) {
    int y  = blockIdx.x;
    int o0 = blockIdx.y * 128;
    int b  = blockIdx.z;
    int tid = threadIdx.x;
    int tr = tid >> 4;   // 0..15 -> 8 outputs each
    int tc = tid & 15;   // 0..15 -> 8 pixels each

    __shared__ float As[36][128];       // [k = cl*9+tap][o]
    __shared__ float Bs[4][3][132];     // [cl][dy][x+1], halo zeroed

    float acc[8][8];
#pragma unroll
    for (int m = 0; m < 8; ++m)
#pragma unroll
        for (int n = 0; n < 8; ++n) acc[m][n] = 0.f;

    for (int cb = 0; cb < 32; ++cb) {
        for (int i = tid; i < 36 * 128; i += 256) {
            int o = i / 36, k = i % 36;
            int cl = k / 9, tap = k % 9;
            As[k][o] = g_Weff[(o0 + o) * 1152 + (cb * 4 + cl) * 9 + tap];
        }
        for (int i = tid; i < 4 * 3 * 132; i += 256) {
            int cl = i / 396;
            int rr = (i / 132) % 3;
            int pos = i % 132;
            int xi = pos - 1;
            int yy = y + rr - 1;
            float v = 0.f;
            if (pos < 130 && (unsigned)xi < 128u && (unsigned)yy < 128u)
                v = X[((size_t)(b * 128 + cb * 4 + cl) * 128 + yy) * 128 + xi];
            Bs[cl][rr][pos] = v;
        }
        __syncthreads();

#pragma unroll
        for (int cl = 0; cl < 4; ++cl) {
#pragma unroll
            for (int dy = 0; dy < 3; ++dy) {
                float bw[10];
#pragma unroll
                for (int n = 0; n < 10; ++n) bw[n] = Bs[cl][dy][tc * 8 + n];
#pragma unroll
                for (int dx = 0; dx < 3; ++dx) {
                    int k = cl * 9 + dy * 3 + dx;
                    float a[8];
#pragma unroll
                    for (int m = 0; m < 8; ++m) a[m] = As[k][tr * 8 + m];
#pragma unroll
                    for (int m = 0; m < 8; ++m)
#pragma unroll
                        for (int n = 0; n < 8; ++n)
                            acc[m][n] = fmaf(a[m], bw[n + dx], acc[m][n]);
                }
            }
        }
        __syncthreads();
    }

    // epilogue: position-dependent bias-through-conv term + dw bias
    int yv0 = (y >= 1), yv2 = (y <= 126);
#pragma unroll
    for (int m = 0; m < 8; ++m) {
        int o = o0 + tr * 8 + m;
        float t[9];
#pragma unroll
        for (int q = 0; q < 9; ++q) t[q] = g_tb[o * 9 + q];
        float rs0 = (yv0 ? t[0] : 0.f) + t[3] + (yv2 ? t[6] : 0.f);
        float rs1 = (yv0 ? t[1] : 0.f) + t[4] + (yv2 ? t[7] : 0.f);
        float rs2 = (yv0 ? t[2] : 0.f) + t[5] + (yv2 ? t[8] : 0.f);
        float base = dwb[o] + rs1;
        float* outp = g_qkv2 + (size_t)(b * 384 + o) * SPATIAL + y * 128 + tc * 8;
#pragma unroll
        for (int n = 0; n < 8; ++n) {
            int x = tc * 8 + n;
            outp[n] = acc[m][n] + base + (x >= 1 ? rs0 : 0.f) + (x <= 126 ? rs2 : 0.f);
        }
    }
}

// ---------------------------------------------------------------------------
// P3: inverse L2 norms for q (ch 0..127) and k (ch 128..255) rows.
// ---------------------------------------------------------------------------
__global__ void norms_kernel() {
    int r  = blockIdx.x;          // 0..511
    int qk = r >> 8;
    int b  = (r >> 7) & 1;
    int ch = r & 127;
    const float* row = g_qkv2 + (size_t)(b * 384 + qk * 128 + ch) * SPATIAL;
    int tid = threadIdx.x;
    float s = 0.f;
    for (int i = tid; i < SPATIAL; i += 256) {
        float v = row[i];
        s = fmaf(v, v, s);
    }
    __shared__ float red[256];
    red[tid] = s;
    __syncthreads();
    for (int st = 128; st > 0; st >>= 1) {
        if (tid < st) red[tid] += red[tid + st];
        __syncthreads();
    }
    if (tid == 0) g_inv[r] = 1.f / fmaxf(sqrtf(red[0]), 1e-12f);
}

__global__ void zero_attnP() {
    int i = blockIdx.x * 256 + threadIdx.x;
    if (i < 8192) g_attnP[i] = 0.f;
}

// ---------------------------------------------------------------------------
// P4: attn partial sums. Grid (16 K-slices, 8 bh). Each block: full 32x32
// tile over its 1024-wide K slice; atomicAdd into g_attnP.
// ---------------------------------------------------------------------------
__global__ void attn_partial() {
    int slice = blockIdx.x;
    int bh = blockIdx.y;
    int b = bh >> 2, h = bh & 3;
    const float* qb = g_qkv2 + (size_t)(b * 384 + h * 32) * SPATIAL;
    const float* kb = g_qkv2 + (size_t)(b * 384 + 128 + h * 32) * SPATIAL;

    __shared__ float qs[32][65], ks[32][65];
    int tid = threadIdx.x;
    int c = tid >> 3;
    int d0 = (tid & 7) * 4;
    float acc[4] = {0.f, 0.f, 0.f, 0.f};

    for (int sub = 0; sub < 16; ++sub) {
        int s0 = slice * 1024 + sub * 64;
        for (int i = tid; i < 2048; i += 256) {
            int cc = i >> 6, kk = i & 63;
            qs[cc][kk] = qb[(size_t)cc * SPATIAL + s0 + kk];
            ks[cc][kk] = kb[(size_t)cc * SPATIAL + s0 + kk];
        }
        __syncthreads();
#pragma unroll 8
        for (int kk = 0; kk < 64; ++kk) {
            float qv = qs[c][kk];
#pragma unroll
            for (int j = 0; j < 4; ++j)
                acc[j] = fmaf(qv, ks[d0 + j][kk], acc[j]);
        }
        __syncthreads();
    }
#pragma unroll
    for (int j = 0; j < 4; ++j)
        atomicAdd(&g_attnP[(bh * 32 + c) * 32 + d0 + j], acc[j]);
}

// ---------------------------------------------------------------------------
// P5: softmax over d (32) with inv-norm and temperature fused in.
// ---------------------------------------------------------------------------
__global__ void softmax_kernel(const float* __restrict__ temp) {
    int row = blockIdx.x;         // bh*32 + c
    int bh = row >> 5, c = row & 31;
    int b = bh >> 2, h = bh & 3;
    int d = threadIdx.x;

    float invq = g_inv[b * 128 + h * 32 + c];
    float invk = g_inv[256 + b * 128 + h * 32 + d];
    float v = g_attnP[row * 32 + d] * invq * invk * temp[h];

    float mx = v;
#pragma unroll
    for (int off = 16; off; off >>= 1)
        mx = fmaxf(mx, __shfl_xor_sync(0xffffffffu, mx, off));
    float e = expf(v - mx);
    float s = e;
#pragma unroll
    for (int off = 16; off; off >>= 1)
        s += __shfl_xor_sync(0xffffffffu, s, off);
    g_attn[row * 32 + d] = e / s;
}

// ---------------------------------------------------------------------------
// P6: out = attn @ v. Grid (64 s-tiles, 8 bh), 256 thr, 1 pixel each.
// ---------------------------------------------------------------------------
__global__ void attn_v() {
    int bh = blockIdx.y;
    int b = bh >> 2, h = bh & 3;
    int s = blockIdx.x * 256 + threadIdx.x;

    __shared__ float A[1024];
    for (int i = threadIdx.x; i < 1024; i += 256) A[i] = g_attn[bh * 1024 + i];
    __syncthreads();

    const float* vb = g_qkv2 + (size_t)(b * 384 + 256 + h * 32) * SPATIAL + s;
    float vv[32];
#pragma unroll
    for (int d = 0; d < 32; ++d) vv[d] = vb[(size_t)d * SPATIAL];

    float* ob = g_av + (size_t)(b * 128 + h * 32) * SPATIAL + s;
#pragma unroll
    for (int cc = 0; cc < 32; ++cc) {
        float o = 0.f;
#pragma unroll
        for (int d = 0; d < 32; ++d)
            o = fmaf(A[cc * 32 + d], vv[d], o);
        ob[(size_t)cc * SPATIAL] = o;
    }
}

// ---------------------------------------------------------------------------
// P7: po 1x1 conv as SGEMM 128x128xK128, tile 128(M) x 128(N), 8x8/thread.
// ---------------------------------------------------------------------------
__global__ __launch_bounds__(256, 2)
void po_gemm(const float* __restrict__ pob, float* __restrict__ out) {
    int s0 = blockIdx.x * 128;
    int b  = blockIdx.z;
    int tid = threadIdx.x;
    int tr = tid >> 4, tc = tid & 15;

    __shared__ float As[16][128];
    __shared__ float Bs[16][132];

    float acc[8][8];
#pragma unroll
    for (int m = 0; m < 8; ++m)
#pragma unroll
        for (int n = 0; n < 8; ++n) acc[m][n] = 0.f;

    for (int cb = 0; cb < 8; ++cb) {
        for (int i = tid; i < 2048; i += 256) {
            int o = i >> 4, kk = i & 15;
            As[kk][o] = g_Wpo[o * 128 + cb * 16 + kk];
        }
        for (int i = tid; i < 2048; i += 256) {
            int kk = i >> 7, sx = i & 127;
            Bs[kk][sx] = g_av[(size_t)(b * 128 + cb * 16 + kk) * SPATIAL + s0 + sx];
        }
        __syncthreads();
#pragma unroll
        for (int kk = 0; kk < 16; ++kk) {
            float a[8], bv[8];
#pragma unroll
            for (int m = 0; m < 8; ++m) a[m] = As[kk][tr * 8 + m];
#pragma unroll
            for (int n = 0; n < 8; ++n) bv[n] = Bs[kk][tc * 8 + n];
#pragma unroll
            for (int m = 0; m < 8; ++m)
#pragma unroll
                for (int n = 0; n < 8; ++n)
                    acc[m][n] = fmaf(a[m], bv[n], acc[m][n]);
        }
        __syncthreads();
    }

#pragma unroll
    for (int m = 0; m < 8; ++m) {
        int o = tr * 8 + m;
        float bias = pob[o];
        float* op = out + (size_t)(b * 128 + o) * SPATIAL + s0 + tc * 8;
#pragma unroll
        for (int n = 0; n < 8; ++n) op[n] = acc[m][n] + bias;
    }
}

// ---------------------------------------------------------------------------
extern "C" void kernel_launch(void* const* d_in, const int* in_sizes, int n_in,
                              void* d_out, int out_size) {
    const float* x     = (const float*)d_in[0];
    const float* qkv_r = (const float*)d_in[1];
    const float* qkv_i = (const float*)d_in[2];
    const float* qkv_j = (const float*)d_in[3];
    const float* qkv_k = (const float*)d_in[4];
    const float* qkv_b = (const float*)d_in[5];
    const float* dw_r  = (const float*)d_in[6];
    const float* dw_i  = (const float*)d_in[7];
    const float* dw_j  = (const float*)d_in[8];
    const float* dw_k  = (const float*)d_in[9];
    const float* dw_b  = (const float*)d_in[10];
    const float* po_r  = (const float*)d_in[11];
    const float* po_i  = (const float*)d_in[12];
    const float* po_j  = (const float*)d_in[13];
    const float* po_k  = (const float*)d_in[14];
    const float* po_b  = (const float*)d_in[15];
    const float* temp  = (const float*)d_in[16];
    float* out = (float*)d_out;

    // P0: weight expansion
    expand_hamilton<<<192, 256>>>(qkv_r, qkv_i, qkv_j, qkv_k, 0, 96, 32, 1);
    expand_hamilton<<<5184, 256>>>(dw_r, dw_i, dw_j, dw_k, 1, 96, 96, 9);
    expand_hamilton<<<64, 256>>>(po_r, po_i, po_j, po_k, 2, 32, 32, 1);

    // P1: fold 1x1 into 3x3
    make_weff<<<3456, 128>>>(qkv_b);

    // P2: fused conv (dominant)
    conv_fused<<<dim3(128, 3, 2), 256>>>(x, dw_b);

    // P3..P5: attention
    norms_kernel<<<512, 256>>>();
    zero_attnP<<<32, 256>>>();
    attn_partial<<<dim3(16, 8), 256>>>();
    softmax_kernel<<<256, 32>>>(temp);
    attn_v<<<dim3(64, 8), 256>>>();

    // P7: output projection
    po_gemm<<<dim3(128, 1, 2), 256>>>(po_b, out);
}

// round 2
// speedup vs baseline: 1.0346x; 1.0346x over previous
#include <cuda_runtime.h>
#include <math.h>

// ---------------------------------------------------------------------------
// QAttention: fused quaternion-conv channel-attention, round 2.
//   P0 expand Hamilton blocks -> full weights
//   P1 Weff[o][c][tap] = Wdw_tap @ Wqkv  (tiled GEMM)   + tb bias fold
//   P2 fused 3x3 conv, fp32x2 packed FFMA2, q/k sumsq fused in epilogue
//   P3 norms finish (tiny)
//   P4 attn logits (K-split + atomics)
//   P5 softmax (inv-norm + temperature fused)
//   P6 M2 = Wpo @ blockdiag(attn)   (tiny)
//   P7 out = M2 @ v + po_b  (fp32x2 GEMM, reads v straight from qkv2)
// ---------------------------------------------------------------------------

#define SPATIAL 16384
typedef unsigned long long u64;

__device__ __forceinline__ u64 pack2(float lo, float hi) {
    u64 r; asm("mov.b64 %0,{%1,%2};" : "=l"(r) : "f"(lo), "f"(hi)); return r;
}
__device__ __forceinline__ float2 unpack2(u64 v) {
    float2 f; asm("mov.b64 {%0,%1},%2;" : "=f"(f.x), "=f"(f.y) : "l"(v)); return f;
}
__device__ __forceinline__ u64 fma2(u64 a, u64 b, u64 c) {
    u64 d; asm("fma.rn.f32x2 %0,%1,%2,%3;" : "=l"(d) : "l"(a), "l"(b), "l"(c)); return d;
}

// scratch (device globals; no allocation allowed)
__device__ float g_Wqkv[384 * 128];
__device__ float g_Wdw[384 * 384 * 9];
__device__ float g_Wpo[128 * 128];
__device__ float g_Weff[384 * 128 * 9];
__device__ float g_tb[384 * 9];
__device__ float g_qkv2[2 * 384 * SPATIAL];   // 50.3 MB
__device__ float g_attnP[2 * 4 * 32 * 32];
__device__ float g_attn[2 * 4 * 32 * 32];
__device__ float g_inv[2 * 2 * 128];          // [qk][b][ch]
__device__ float g_ss[2 * 256];               // [b][o] sumsq for q,k rows
__device__ float g_M2[2 * 128 * 128];         // fused po@attn

// ---------------------------------------------------------------------------
// P0: Hamilton-product block expansion.
// ---------------------------------------------------------------------------
__global__ void expand_hamilton(const float* __restrict__ r,
                                const float* __restrict__ i_,
                                const float* __restrict__ j_,
                                const float* __restrict__ k_,
                                int dest, int O4, int C4, int T) {
    int idx = blockIdx.x * blockDim.x + threadIdx.x;
    int total = 16 * O4 * C4 * T;
    if (idx >= total) return;

    int tap = idx % T;
    int rem = idx / T;
    int C = 4 * C4;
    int c = rem % C;
    int o = rem / C;
    int br = o / O4, oo = o % O4;
    int bc = c / C4, cc = c % C4;

    const int   src[16] = {0,1,2,3, 1,0,3,2, 2,3,0,1, 3,2,1,0};
    const float sgn[16] = {1.f,-1.f,-1.f,-1.f, 1.f,1.f,-1.f,1.f,
                           1.f,1.f,1.f,-1.f,  1.f,-1.f,1.f,1.f};
    const float* comp[4] = {r, i_, j_, k_};

    float v = sgn[br * 4 + bc] * comp[src[br * 4 + bc]][(oo * C4 + cc) * T + tap];
    float* out = (dest == 0) ? g_Wqkv : (dest == 1) ? g_Wdw : g_Wpo;
    out[idx] = v;
}

// ---------------------------------------------------------------------------
// P1a: Weff as 27 tiled GEMMs: per (o-tile 128, tap): [128x128] = Wdw_tap @ Wqkv
// ---------------------------------------------------------------------------
__global__ __launch_bounds__(256)
void weff_gemm() {
    int o0  = blockIdx.x * 128;
    int tap = blockIdx.y;
    int tid = threadIdx.x;
    int tr = tid >> 4, tc = tid & 15;

    __shared__ float As[16][128];   // [kk][o]
    __shared__ float Bs[16][132];   // [kk][c]

    float acc[8][8];
#pragma unroll
    for (int m = 0; m < 8; ++m)
#pragma unroll
        for (int n = 0; n < 8; ++n) acc[m][n] = 0.f;

    for (int cb = 0; cb < 24; ++cb) {
        for (int i = tid; i < 2048; i += 256) {
            int oo = i >> 4, kk = i & 15;
            As[kk][oo] = g_Wdw[((o0 + oo) * 384 + cb * 16 + kk) * 9 + tap];
        }
        for (int i = tid; i < 2048; i += 256) {
            int kk = i >> 7, c = i & 127;
            Bs[kk][c] = g_Wqkv[(cb * 16 + kk) * 128 + c];
        }
        __syncthreads();
#pragma unroll
        for (int kk = 0; kk < 16; ++kk) {
            float a[8], bv[8];
#pragma unroll
            for (int m = 0; m < 8; ++m) a[m] = As[kk][tr * 8 + m];
#pragma unroll
            for (int n = 0; n < 8; ++n) bv[n] = Bs[kk][tc * 8 + n];
#pragma unroll
            for (int m = 0; m < 8; ++m)
#pragma unroll
                for (int n = 0; n < 8; ++n)
                    acc[m][n] = fmaf(a[m], bv[n], acc[m][n]);
        }
        __syncthreads();
    }
#pragma unroll
    for (int m = 0; m < 8; ++m)
#pragma unroll
        for (int n = 0; n < 8; ++n)
            g_Weff[(o0 + tr * 8 + m) * 1152 + (tc * 8 + n) * 9 + tap] = acc[m][n];
}

// ---------------------------------------------------------------------------
// P1b: tb[o][tap] = sum_m Wdw[o][m][tap] * qkv_b[m]
// ---------------------------------------------------------------------------
__global__ void make_tb(const float* __restrict__ qkv_b) {
    int o = blockIdx.x;
    int tid = threadIdx.x;
    __shared__ float red[128];
    for (int tap = 0; tap < 9; ++tap) {
        float s = 0.f;
        for (int m = tid; m < 384; m += 128)
            s = fmaf(g_Wdw[(o * 384 + m) * 9 + tap], qkv_b[m], s);
        red[tid] = s;
        __syncthreads();
        for (int st = 64; st > 0; st >>= 1) {
            if (tid < st) red[tid] += red[tid + st];
            __syncthreads();
        }
        if (tid == 0) g_tb[o * 9 + tap] = red[0];
        __syncthreads();
    }
}

__global__ void zero_scratch() {
    int i = blockIdx.x * 256 + threadIdx.x;
    if (i < 8192) g_attnP[i] = 0.f;
    if (i < 512)  g_ss[i] = 0.f;
}

// ---------------------------------------------------------------------------
// P2: fused 3x3 conv as implicit GEMM, fp32x2 (FFMA2).
// Block: one image row y, 128 outputs (pairs packed in f32x2 lanes), one batch.
// Epilogue adds per-tap-valid bias and accumulates q/k row sumsq via atomics.
// ---------------------------------------------------------------------------
__global__ __launch_bounds__(256, 2)
void conv_fused(const float* __restrict__ X, const float* __restrict__ dwb) {
    int y  = blockIdx.x;
    int o0 = blockIdx.y * 128;
    int b  = blockIdx.z;
    int tid = threadIdx.x;
    int tr = tid >> 4;   // 0..15 -> 8 outputs (4 f32x2 pairs)
    int tc = tid & 15;   // 0..15 -> 8 pixels

    __shared__ float As[36][128];       // [k = cl*9+tap][o]
    __shared__ float Bs[4][3][132];     // [cl][dy][x+1], halo zeroed

    u64 acc2[4][8];
#pragma unroll
    for (int mp = 0; mp < 4; ++mp)
#pragma unroll
        for (int n = 0; n < 8; ++n) acc2[mp][n] = 0ull;

    for (int cb = 0; cb < 32; ++cb) {
        for (int i = tid; i < 36 * 128; i += 256) {
            int o = i / 36, k = i % 36;
            As[k][o] = g_Weff[(o0 + o) * 1152 + cb * 36 + k];
        }
        for (int i = tid; i < 4 * 3 * 132; i += 256) {
            int cl = i / 396;
            int rr = (i / 132) % 3;
            int pos = i % 132;
            int xi = pos - 1;
            int yy = y + rr - 1;
            float v = 0.f;
            if (pos < 130 && (unsigned)xi < 128u && (unsigned)yy < 128u)
                v = X[((size_t)(b * 128 + cb * 4 + cl) * 128 + yy) * 128 + xi];
            Bs[cl][rr][pos] = v;
        }
        __syncthreads();

#pragma unroll
        for (int cl = 0; cl < 4; ++cl) {
#pragma unroll
            for (int dy = 0; dy < 3; ++dy) {
                const float* brow = &Bs[cl][dy][tc * 8];
                float4 v0 = *(const float4*)brow;
                float4 v1 = *(const float4*)(brow + 4);
                float e8 = brow[8], e9 = brow[9];
                u64 bb[10];
                bb[0] = pack2(v0.x, v0.x); bb[1] = pack2(v0.y, v0.y);
                bb[2] = pack2(v0.z, v0.z); bb[3] = pack2(v0.w, v0.w);
                bb[4] = pack2(v1.x, v1.x); bb[5] = pack2(v1.y, v1.y);
                bb[6] = pack2(v1.z, v1.z); bb[7] = pack2(v1.w, v1.w);
                bb[8] = pack2(e8, e8);     bb[9] = pack2(e9, e9);
#pragma unroll
                for (int dx = 0; dx < 3; ++dx) {
                    int k = cl * 9 + dy * 3 + dx;
                    u64 a2[4];
#pragma unroll
                    for (int mp = 0; mp < 4; ++mp)
                        a2[mp] = *(const u64*)&As[k][tr * 8 + 2 * mp];
#pragma unroll
                    for (int mp = 0; mp < 4; ++mp)
#pragma unroll
                        for (int n = 0; n < 8; ++n)
                            acc2[mp][n] = fma2(a2[mp], bb[n + dx], acc2[mp][n]);
                }
            }
        }
        __syncthreads();
    }

    // epilogue: position-dependent bias-through-conv + dw bias + q/k sumsq
    int yv0 = (y >= 1), yv2 = (y <= 126);
    bool doss = (o0 < 256);
#pragma unroll
    for (int mp = 0; mp < 4; ++mp) {
        int oA = o0 + tr * 8 + 2 * mp;    // even output; pair is (oA, oA+1)
        float rs0[2], rs2[2], base[2];
#pragma unroll
        for (int hh = 0; hh < 2; ++hh) {
            const float* t = &g_tb[(oA + hh) * 9];
            rs0[hh] = (yv0 ? t[0] : 0.f) + t[3] + (yv2 ? t[6] : 0.f);
            float rs1 = (yv0 ? t[1] : 0.f) + t[4] + (yv2 ? t[7] : 0.f);
            rs2[hh] = (yv0 ? t[2] : 0.f) + t[5] + (yv2 ? t[8] : 0.f);
            base[hh] = dwb[oA + hh] + rs1;
        }
        float* out0 = g_qkv2 + (size_t)(b * 384 + oA) * SPATIAL + y * 128 + tc * 8;
        float* out1 = out0 + SPATIAL;
        float ss0 = 0.f, ss1 = 0.f;
#pragma unroll
        for (int n = 0; n < 8; ++n) {
            int x = tc * 8 + n;
            float2 v = unpack2(acc2[mp][n]);
            float l = (x >= 1) ? 1.f : 0.f;
            float rr = (x <= 126) ? 1.f : 0.f;
            v.x += base[0] + l * rs0[0] + rr * rs2[0];
            v.y += base[1] + l * rs0[1] + rr * rs2[1];
            out0[n] = v.x; out1[n] = v.y;
            ss0 = fmaf(v.x, v.x, ss0);
            ss1 = fmaf(v.y, v.y, ss1);
        }
        if (doss) {
#pragma unroll
            for (int off = 8; off; off >>= 1) {
                ss0 += __shfl_xor_sync(0xffffffffu, ss0, off);
                ss1 += __shfl_xor_sync(0xffffffffu, ss1, off);
            }
            if ((tid & 15) == 0) {
                atomicAdd(&g_ss[b * 256 + oA], ss0);
                atomicAdd(&g_ss[b * 256 + oA + 1], ss1);
            }
        }
    }
}

// ---------------------------------------------------------------------------
// P3: finish inverse norms from fused sumsq.
// ---------------------------------------------------------------------------
__global__ void norms_finish() {
    int r = blockIdx.x * 256 + threadIdx.x;
    if (r >= 512) return;
    int qk = r >> 8;
    int b  = (r >> 7) & 1;
    int ch = r & 127;
    float ss = g_ss[b * 256 + qk * 128 + ch];
    g_inv[r] = 1.f / fmaxf(sqrtf(ss), 1e-12f);
}

// ---------------------------------------------------------------------------
// P4: attn partial sums (K-split + atomics).
// ---------------------------------------------------------------------------
__global__ void attn_partial() {
    int slice = blockIdx.x;
    int bh = blockIdx.y;
    int b = bh >> 2, h = bh & 3;
    const float* qb = g_qkv2 + (size_t)(b * 384 + h * 32) * SPATIAL;
    const float* kb = g_qkv2 + (size_t)(b * 384 + 128 + h * 32) * SPATIAL;

    __shared__ float qs[32][65], ks[32][65];
    int tid = threadIdx.x;
    int c = tid >> 3;
    int d0 = (tid & 7) * 4;
    float acc[4] = {0.f, 0.f, 0.f, 0.f};

    for (int sub = 0; sub < 16; ++sub) {
        int s0 = slice * 1024 + sub * 64;
        for (int i = tid; i < 2048; i += 256) {
            int cc = i >> 6, kk = i & 63;
            qs[cc][kk] = qb[(size_t)cc * SPATIAL + s0 + kk];
            ks[cc][kk] = kb[(size_t)cc * SPATIAL + s0 + kk];
        }
        __syncthreads();
#pragma unroll 8
        for (int kk = 0; kk < 64; ++kk) {
            float qv = qs[c][kk];
#pragma unroll
            for (int j = 0; j < 4; ++j)
                acc[j] = fmaf(qv, ks[d0 + j][kk], acc[j]);
        }
        __syncthreads();
    }
#pragma unroll
    for (int j = 0; j < 4; ++j)
        atomicAdd(&g_attnP[(bh * 32 + c) * 32 + d0 + j], acc[j]);
}

// ---------------------------------------------------------------------------
// P5: softmax with inv-norms and temperature fused in.
// ---------------------------------------------------------------------------
__global__ void softmax_kernel(const float* __restrict__ temp) {
    int row = blockIdx.x;         // bh*32 + c
    int bh = row >> 5, c = row & 31;
    int b = bh >> 2, h = bh & 3;
    int d = threadIdx.x;

    float invq = g_inv[b * 128 + h * 32 + c];
    float invk = g_inv[256 + b * 128 + h * 32 + d];
    float v = g_attnP[row * 32 + d] * invq * invk * temp[h];

    float mx = v;
#pragma unroll
    for (int off = 16; off; off >>= 1)
        mx = fmaxf(mx, __shfl_xor_sync(0xffffffffu, mx, off));
    float e = expf(v - mx);
    float s = e;
#pragma unroll
    for (int off = 16; off; off >>= 1)
        s += __shfl_xor_sync(0xffffffffu, s, off);
    g_attn[row * 32 + d] = e / s;
}

// ---------------------------------------------------------------------------
// P6: M2[b][o][h*32+d] = sum_c Wpo[o][h*32+c] * attn[bh][c][d]
// ---------------------------------------------------------------------------
__global__ void make_M2() {
    int b = blockIdx.x, h = blockIdx.y;
    int bh = b * 4 + h;
    int tid = threadIdx.x;

    __shared__ float A[32][33];
    __shared__ float W[128][33];

    for (int i = tid; i < 1024; i += 256) {
        int c = i >> 5, d = i & 31;
        A[c][d] = g_attn[(bh * 32 + c) * 32 + d];
    }
    for (int i = tid; i < 4096; i += 256) {
        int o = i >> 5, c = i & 31;
        W[o][c] = g_Wpo[o * 128 + h * 32 + c];
    }
    __syncthreads();

    int o = tid >> 1;
    int d0 = (tid & 1) * 16;
#pragma unroll
    for (int dd = 0; dd < 16; ++dd) {
        int d = d0 + dd;
        float s = 0.f;
#pragma unroll
        for (int c = 0; c < 32; ++c)
            s = fmaf(W[o][c], A[c][d], s);
        g_M2[b * 16384 + o * 128 + h * 32 + d] = s;
    }
}

// ---------------------------------------------------------------------------
// P7: out[b][o][s] = sum_dg M2[b][o][dg] * v[b][dg][s] + po_b[o]  (fp32x2)
// ---------------------------------------------------------------------------
__global__ __launch_bounds__(256, 2)
void final_gemm(const float* __restrict__ pob, float* __restrict__ out) {
    int s0 = blockIdx.x * 128;
    int b  = blockIdx.z;
    int tid = threadIdx.x;
    int tr = tid >> 4, tc = tid & 15;

    __shared__ float As[16][128];
    __shared__ float Bs[16][132];

    u64 acc2[4][8];
#pragma unroll
    for (int mp = 0; mp < 4; ++mp)
#pragma unroll
        for (int n = 0; n < 8; ++n) acc2[mp][n] = 0ull;

    for (int cb = 0; cb < 8; ++cb) {
        for (int i = tid; i < 2048; i += 256) {
            int o = i >> 4, kk = i & 15;
            As[kk][o] = g_M2[b * 16384 + o * 128 + cb * 16 + kk];
        }
        for (int i = tid; i < 2048; i += 256) {
            int kk = i >> 7, sx = i & 127;
            Bs[kk][sx] = g_qkv2[(size_t)(b * 384 + 256 + cb * 16 + kk) * SPATIAL + s0 + sx];
        }
        __syncthreads();
#pragma unroll
        for (int kk = 0; kk < 16; ++kk) {
            u64 a2[4];
#pragma unroll
            for (int mp = 0; mp < 4; ++mp)
                a2[mp] = *(const u64*)&As[kk][tr * 8 + 2 * mp];
            const float* brow = &Bs[kk][tc * 8];
            float4 w0 = *(const float4*)brow;
            float4 w1 = *(const float4*)(brow + 4);
            u64 bb[8];
            bb[0] = pack2(w0.x, w0.x); bb[1] = pack2(w0.y, w0.y);
            bb[2] = pack2(w0.z, w0.z); bb[3] = pack2(w0.w, w0.w);
            bb[4] = pack2(w1.x, w1.x); bb[5] = pack2(w1.y, w1.y);
            bb[6] = pack2(w1.z, w1.z); bb[7] = pack2(w1.w, w1.w);
#pragma unroll
            for (int mp = 0; mp < 4; ++mp)
#pragma unroll
                for (int n = 0; n < 8; ++n)
                    acc2[mp][n] = fma2(a2[mp], bb[n], acc2[mp][n]);
        }
        __syncthreads();
    }

#pragma unroll
    for (int mp = 0; mp < 4; ++mp) {
        int oA = tr * 8 + 2 * mp;
        float b0 = pob[oA], b1 = pob[oA + 1];
        float* op0 = out + (size_t)(b * 128 + oA) * SPATIAL + s0 + tc * 8;
        float* op1 = op0 + SPATIAL;
#pragma unroll
        for (int n = 0; n < 8; ++n) {
            float2 v = unpack2(acc2[mp][n]);
            op0[n] = v.x + b0;
            op1[n] = v.y + b1;
        }
    }
}

// ---------------------------------------------------------------------------
extern "C" void kernel_launch(void* const* d_in, const int* in_sizes, int n_in,
                              void* d_out, int out_size) {
    const float* x     = (const float*)d_in[0];
    const float* qkv_r = (const float*)d_in[1];
    const float* qkv_i = (const float*)d_in[2];
    const float* qkv_j = (const float*)d_in[3];
    const float* qkv_k = (const float*)d_in[4];
    const float* qkv_b = (const float*)d_in[5];
    const float* dw_r  = (const float*)d_in[6];
    const float* dw_i  = (const float*)d_in[7];
    const float* dw_j  = (const float*)d_in[8];
    const float* dw_k  = (const float*)d_in[9];
    const float* dw_b  = (const float*)d_in[10];
    const float* po_r  = (const float*)d_in[11];
    const float* po_i  = (const float*)d_in[12];
    const float* po_j  = (const float*)d_in[13];
    const float* po_k  = (const float*)d_in[14];
    const float* po_b  = (const float*)d_in[15];
    const float* temp  = (const float*)d_in[16];
    float* out = (float*)d_out;

    // P0: weight expansion
    expand_hamilton<<<192, 256>>>(qkv_r, qkv_i, qkv_j, qkv_k, 0, 96, 32, 1);
    expand_hamilton<<<5184, 256>>>(dw_r, dw_i, dw_j, dw_k, 1, 96, 96, 9);
    expand_hamilton<<<64, 256>>>(po_r, po_i, po_j, po_k, 2, 32, 32, 1);

    // P1: fold 1x1 into 3x3
    weff_gemm<<<dim3(3, 9), 256>>>();
    make_tb<<<384, 128>>>(qkv_b);
    zero_scratch<<<34, 256>>>();

    // P2: fused conv (dominant) with sumsq fused
    conv_fused<<<dim3(128, 3, 2), 256>>>(x, dw_b);

    // P3..P6: attention
    norms_finish<<<2, 256>>>();
    attn_partial<<<dim3(16, 8), 256>>>();
    softmax_kernel<<<256, 32>>>(temp);
    make_M2<<<dim3(2, 4), 256>>>();

    // P7: fused (po @ attn) @ v -> out
    final_gemm<<<dim3(128, 1, 2), 256>>>(po_b, out);
}

// round 3
// speedup vs baseline: 1.0626x; 1.0270x over previous
#include <cuda_runtime.h>
#include <math.h>

// ---------------------------------------------------------------------------
// QAttention: fused quaternion-conv channel-attention, round 3.
//   P0 zero scratch
//   P1 expand Hamilton blocks -> full weights
//   P2 weff_o: Weff[o][c][tap] = sum_m Wdw[o][m][tap]*Wqkv[m][c]  + tb fold
//   P3 fused 3x3 conv, fp32x2 FFMA2, relaxed regs, q/k sumsq fused (6th launch)
//   P4 norms finish
//   P5 attn logits (K-split + atomics)
//   P6 softmax (inv-norm + temperature fused)
//   P7 M2 = Wpo @ blockdiag(attn)
//   P8 out = M2 @ v + po_b
// ---------------------------------------------------------------------------

#define SPATIAL 16384
typedef unsigned long long u64;

__device__ __forceinline__ u64 pack2(float lo, float hi) {
    u64 r; asm("mov.b64 %0,{%1,%2};" : "=l"(r) : "f"(lo), "f"(hi)); return r;
}
__device__ __forceinline__ float2 unpack2(u64 v) {
    float2 f; asm("mov.b64 {%0,%1},%2;" : "=f"(f.x), "=f"(f.y) : "l"(v)); return f;
}
__device__ __forceinline__ u64 fma2(u64 a, u64 b, u64 c) {
    u64 d; asm("fma.rn.f32x2 %0,%1,%2,%3;" : "=l"(d) : "l"(a), "l"(b), "l"(c)); return d;
}

// scratch (device globals; no allocation allowed)
__device__ float g_Wqkv[384 * 128];
__device__ float g_Wdw[384 * 384 * 9];
__device__ float g_Wpo[128 * 128];
__device__ float g_Weff[384 * 128 * 9];
__device__ float g_tb[384 * 9];
__device__ float g_qkv2[2 * 384 * SPATIAL];   // 50.3 MB
__device__ float g_attnP[2 * 4 * 32 * 32];
__device__ float g_attn[2 * 4 * 32 * 32];
__device__ float g_inv[2 * 2 * 128];          // [qk][b][ch]
__device__ float g_ss[2 * 256];               // [b][o] sumsq for q,k rows
__device__ float g_M2[2 * 128 * 128];         // fused po@attn

// ---------------------------------------------------------------------------
// P0: zero attn partials and sumsq accumulators.
// ---------------------------------------------------------------------------
__global__ void zero_scratch() {
    int i = blockIdx.x * 256 + threadIdx.x;
    if (i < 8192) g_attnP[i] = 0.f;
    if (i < 512)  g_ss[i] = 0.f;
}

// ---------------------------------------------------------------------------
// P1: Hamilton-product block expansion.
// ---------------------------------------------------------------------------
__global__ void expand_hamilton(const float* __restrict__ r,
                                const float* __restrict__ i_,
                                const float* __restrict__ j_,
                                const float* __restrict__ k_,
                                int dest, int O4, int C4, int T) {
    int idx = blockIdx.x * blockDim.x + threadIdx.x;
    int total = 16 * O4 * C4 * T;
    if (idx >= total) return;

    int tap = idx % T;
    int rem = idx / T;
    int C = 4 * C4;
    int c = rem % C;
    int o = rem / C;
    int br = o / O4, oo = o % O4;
    int bc = c / C4, cc = c % C4;

    const int   src[16] = {0,1,2,3, 1,0,3,2, 2,3,0,1, 3,2,1,0};
    const float sgn[16] = {1.f,-1.f,-1.f,-1.f, 1.f,1.f,-1.f,1.f,
                           1.f,1.f,1.f,-1.f,  1.f,-1.f,1.f,1.f};
    const float* comp[4] = {r, i_, j_, k_};

    float v = sgn[br * 4 + bc] * comp[src[br * 4 + bc]][(oo * C4 + cc) * T + tap];
    float* out = (dest == 0) ? g_Wqkv : (dest == 1) ? g_Wdw : g_Wpo;
    out[idx] = v;
}

// ---------------------------------------------------------------------------
// P2: Weff per output row. 384 blocks x 128 threads (thread = c).
// Coalesced contiguous Wdw row loads; Wqkv chunked through smem.
// tb[o][tap] folded in (warp 0 partials + shfl reduce).
// ---------------------------------------------------------------------------
__global__ __launch_bounds__(128)
void weff_o(const float* __restrict__ qkv_b) {
    int o = blockIdx.x;
    int c = threadIdx.x;

    __shared__ float wdw_s[288 + 8];      // chunk: 32 m x 9 taps, linear
    __shared__ float wq_s[32 * 128];      // chunk: 32 m x 128 c
    __shared__ float qb_s[384];

    for (int m = c; m < 384; m += 128) qb_s[m] = qkv_b[m];

    float acc[9];
#pragma unroll
    for (int t = 0; t < 9; ++t) acc[t] = 0.f;
    float tbp[9];
#pragma unroll
    for (int t = 0; t < 9; ++t) tbp[t] = 0.f;

    const float* wdw_row = g_Wdw + (size_t)o * 3456;

    for (int cb = 0; cb < 12; ++cb) {
        __syncthreads();
        for (int i = c; i < 288; i += 128)
            wdw_s[i] = wdw_row[cb * 288 + i];
        for (int i = c; i < 4096; i += 128) {
            int m = i >> 7, col = i & 127;
            wq_s[m * 128 + col] = g_Wqkv[(cb * 32 + m) * 128 + col];
        }
        __syncthreads();

#pragma unroll 4
        for (int m = 0; m < 32; ++m) {
            float wq = wq_s[m * 128 + c];
#pragma unroll
            for (int t = 0; t < 9; ++t)
                acc[t] = fmaf(wdw_s[m * 9 + t], wq, acc[t]);
        }
        // tb partials: warp 0, lane = m within chunk
        if (c < 32) {
            float qb = qb_s[cb * 32 + c];
#pragma unroll
            for (int t = 0; t < 9; ++t)
                tbp[t] = fmaf(wdw_s[c * 9 + t], qb, tbp[t]);
        }
    }

#pragma unroll
    for (int t = 0; t < 9; ++t)
        g_Weff[(size_t)o * 1152 + c * 9 + t] = acc[t];

    if (c < 32) {
#pragma unroll
        for (int t = 0; t < 9; ++t) {
            float v = tbp[t];
#pragma unroll
            for (int off = 16; off; off >>= 1)
                v += __shfl_xor_sync(0xffffffffu, v, off);
            if (c == 0) g_tb[o * 9 + t] = v;
        }
    }
}

// ---------------------------------------------------------------------------
// P3: fused 3x3 conv as implicit GEMM, fp32x2 (FFMA2), relaxed regs.
// Block: one image row y, 128 outputs (pairs packed), one batch.
// Epilogue: per-tap-valid bias + q/k row sumsq (atomics).
// ---------------------------------------------------------------------------
__global__ __launch_bounds__(256)
void conv_fused(const float* __restrict__ X, const float* __restrict__ dwb) {
    int y  = blockIdx.x;
    int o0 = blockIdx.y * 128;
    int b  = blockIdx.z;
    int tid = threadIdx.x;
    int tr = tid >> 4;   // 0..15 -> 8 outputs (4 f32x2 pairs)
    int tc = tid & 15;   // 0..15 -> 8 pixels

    __shared__ float As[36][128];       // [k = cl*9+tap][o]
    __shared__ float Bs[4][3][132];     // [cl][dy][x+1], halo zeroed

    u64 acc2[4][8];
#pragma unroll
    for (int mp = 0; mp < 4; ++mp)
#pragma unroll
        for (int n = 0; n < 8; ++n) acc2[mp][n] = 0ull;

    for (int cb = 0; cb < 32; ++cb) {
        for (int i = tid; i < 36 * 128; i += 256) {
            int o = i / 36, k = i % 36;
            As[k][o] = g_Weff[(o0 + o) * 1152 + cb * 36 + k];
        }
        for (int i = tid; i < 4 * 3 * 132; i += 256) {
            int cl = i / 396;
            int rr = (i / 132) % 3;
            int pos = i % 132;
            int xi = pos - 1;
            int yy = y + rr - 1;
            float v = 0.f;
            if (pos < 130 && (unsigned)xi < 128u && (unsigned)yy < 128u)
                v = X[((size_t)(b * 128 + cb * 4 + cl) * 128 + yy) * 128 + xi];
            Bs[cl][rr][pos] = v;
        }
        __syncthreads();

#pragma unroll
        for (int cl = 0; cl < 4; ++cl) {
#pragma unroll
            for (int dy = 0; dy < 3; ++dy) {
                const float* brow = &Bs[cl][dy][tc * 8];
                float4 v0 = *(const float4*)brow;
                float4 v1 = *(const float4*)(brow + 4);
                float e8 = brow[8], e9 = brow[9];
                u64 bb[10];
                bb[0] = pack2(v0.x, v0.x); bb[1] = pack2(v0.y, v0.y);
                bb[2] = pack2(v0.z, v0.z); bb[3] = pack2(v0.w, v0.w);
                bb[4] = pack2(v1.x, v1.x); bb[5] = pack2(v1.y, v1.y);
                bb[6] = pack2(v1.z, v1.z); bb[7] = pack2(v1.w, v1.w);
                bb[8] = pack2(e8, e8);     bb[9] = pack2(e9, e9);
#pragma unroll
                for (int dx = 0; dx < 3; ++dx) {
                    int k = cl * 9 + dy * 3 + dx;
                    u64 a2[4];
#pragma unroll
                    for (int mp = 0; mp < 4; ++mp)
                        a2[mp] = *(const u64*)&As[k][tr * 8 + 2 * mp];
#pragma unroll
                    for (int mp = 0; mp < 4; ++mp)
#pragma unroll
                        for (int n = 0; n < 8; ++n)
                            acc2[mp][n] = fma2(a2[mp], bb[n + dx], acc2[mp][n]);
                }
            }
        }
        __syncthreads();
    }

    // epilogue: position-dependent bias-through-conv + dw bias + q/k sumsq
    int yv0 = (y >= 1), yv2 = (y <= 126);
    bool doss = (o0 < 256);
#pragma unroll
    for (int mp = 0; mp < 4; ++mp) {
        int oA = o0 + tr * 8 + 2 * mp;    // even output; pair is (oA, oA+1)
        float rs0[2], rs2[2], base[2];
#pragma unroll
        for (int hh = 0; hh < 2; ++hh) {
            const float* t = &g_tb[(oA + hh) * 9];
            rs0[hh] = (yv0 ? t[0] : 0.f) + t[3] + (yv2 ? t[6] : 0.f);
            float rs1 = (yv0 ? t[1] : 0.f) + t[4] + (yv2 ? t[7] : 0.f);
            rs2[hh] = (yv0 ? t[2] : 0.f) + t[5] + (yv2 ? t[8] : 0.f);
            base[hh] = dwb[oA + hh] + rs1;
        }
        float* out0 = g_qkv2 + (size_t)(b * 384 + oA) * SPATIAL + y * 128 + tc * 8;
        float* out1 = out0 + SPATIAL;
        float ss0 = 0.f, ss1 = 0.f;
#pragma unroll
        for (int n = 0; n < 8; ++n) {
            int x = tc * 8 + n;
            float2 v = unpack2(acc2[mp][n]);
            float l = (x >= 1) ? 1.f : 0.f;
            float rr = (x <= 126) ? 1.f : 0.f;
            v.x += base[0] + l * rs0[0] + rr * rs2[0];
            v.y += base[1] + l * rs0[1] + rr * rs2[1];
            out0[n] = v.x; out1[n] = v.y;
            ss0 = fmaf(v.x, v.x, ss0);
            ss1 = fmaf(v.y, v.y, ss1);
        }
        if (doss) {
#pragma unroll
            for (int off = 8; off; off >>= 1) {
                ss0 += __shfl_xor_sync(0xffffffffu, ss0, off);
                ss1 += __shfl_xor_sync(0xffffffffu, ss1, off);
            }
            if ((tid & 15) == 0) {
                atomicAdd(&g_ss[b * 256 + oA], ss0);
                atomicAdd(&g_ss[b * 256 + oA + 1], ss1);
            }
        }
    }
}

// ---------------------------------------------------------------------------
// P4: finish inverse norms from fused sumsq.
// ---------------------------------------------------------------------------
__global__ void norms_finish() {
    int r = blockIdx.x * 256 + threadIdx.x;
    if (r >= 512) return;
    int qk = r >> 8;
    int b  = (r >> 7) & 1;
    int ch = r & 127;
    float ss = g_ss[b * 256 + qk * 128 + ch];
    g_inv[r] = 1.f / fmaxf(sqrtf(ss), 1e-12f);
}

// ---------------------------------------------------------------------------
// P5: attn partial sums (K-split + atomics).
// ---------------------------------------------------------------------------
__global__ void attn_partial() {
    int slice = blockIdx.x;
    int bh = blockIdx.y;
    int b = bh >> 2, h = bh & 3;
    const float* qb = g_qkv2 + (size_t)(b * 384 + h * 32) * SPATIAL;
    const float* kb = g_qkv2 + (size_t)(b * 384 + 128 + h * 32) * SPATIAL;

    __shared__ float qs[32][65], ks[32][65];
    int tid = threadIdx.x;
    int c = tid >> 3;
    int d0 = (tid & 7) * 4;
    float acc[4] = {0.f, 0.f, 0.f, 0.f};

    for (int sub = 0; sub < 16; ++sub) {
        int s0 = slice * 1024 + sub * 64;
        for (int i = tid; i < 2048; i += 256) {
            int cc = i >> 6, kk = i & 63;
            qs[cc][kk] = qb[(size_t)cc * SPATIAL + s0 + kk];
            ks[cc][kk] = kb[(size_t)cc * SPATIAL + s0 + kk];
        }
        __syncthreads();
#pragma unroll 8
        for (int kk = 0; kk < 64; ++kk) {
            float qv = qs[c][kk];
#pragma unroll
            for (int j = 0; j < 4; ++j)
                acc[j] = fmaf(qv, ks[d0 + j][kk], acc[j]);
        }
        __syncthreads();
    }
#pragma unroll
    for (int j = 0; j < 4; ++j)
        atomicAdd(&g_attnP[(bh * 32 + c) * 32 + d0 + j], acc[j]);
}

// ---------------------------------------------------------------------------
// P6: softmax with inv-norms and temperature fused in.
// ---------------------------------------------------------------------------
__global__ void softmax_kernel(const float* __restrict__ temp) {
    int row = blockIdx.x;         // bh*32 + c
    int bh = row >> 5, c = row & 31;
    int b = bh >> 2, h = bh & 3;
    int d = threadIdx.x;

    float invq = g_inv[b * 128 + h * 32 + c];
    float invk = g_inv[256 + b * 128 + h * 32 + d];
    float v = g_attnP[row * 32 + d] * invq * invk * temp[h];

    float mx = v;
#pragma unroll
    for (int off = 16; off; off >>= 1)
        mx = fmaxf(mx, __shfl_xor_sync(0xffffffffu, mx, off));
    float e = expf(v - mx);
    float s = e;
#pragma unroll
    for (int off = 16; off; off >>= 1)
        s += __shfl_xor_sync(0xffffffffu, s, off);
    g_attn[row * 32 + d] = e / s;
}

// ---------------------------------------------------------------------------
// P7: M2[b][o][h*32+d] = sum_c Wpo[o][h*32+c] * attn[bh][c][d]
// ---------------------------------------------------------------------------
__global__ void make_M2() {
    int b = blockIdx.x, h = blockIdx.y;
    int bh = b * 4 + h;
    int tid = threadIdx.x;

    __shared__ float A[32][33];
    __shared__ float W[128][33];

    for (int i = tid; i < 1024; i += 256) {
        int c = i >> 5, d = i & 31;
        A[c][d] = g_attn[(bh * 32 + c) * 32 + d];
    }
    for (int i = tid; i < 4096; i += 256) {
        int o = i >> 5, c = i & 31;
        W[o][c] = g_Wpo[o * 128 + h * 32 + c];
    }
    __syncthreads();

    int o = tid >> 1;
    int d0 = (tid & 1) * 16;
#pragma unroll
    for (int dd = 0; dd < 16; ++dd) {
        int d = d0 + dd;
        float s = 0.f;
#pragma unroll
        for (int c = 0; c < 32; ++c)
            s = fmaf(W[o][c], A[c][d], s);
        g_M2[b * 16384 + o * 128 + h * 32 + d] = s;
    }
}

// ---------------------------------------------------------------------------
// P8: out[b][o][s] = sum_dg M2[b][o][dg] * v[b][dg][s] + po_b[o]  (fp32x2)
// ---------------------------------------------------------------------------
__global__ __launch_bounds__(256)
void final_gemm(const float* __restrict__ pob, float* __restrict__ out) {
    int s0 = blockIdx.x * 128;
    int b  = blockIdx.z;
    int tid = threadIdx.x;
    int tr = tid >> 4, tc = tid & 15;

    __shared__ float As[16][128];
    __shared__ float Bs[16][132];

    u64 acc2[4][8];
#pragma unroll
    for (int mp = 0; mp < 4; ++mp)
#pragma unroll
        for (int n = 0; n < 8; ++n) acc2[mp][n] = 0ull;

    for (int cb = 0; cb < 8; ++cb) {
        for (int i = tid; i < 2048; i += 256) {
            int o = i >> 4, kk = i & 15;
            As[kk][o] = g_M2[b * 16384 + o * 128 + cb * 16 + kk];
        }
        for (int i = tid; i < 2048; i += 256) {
            int kk = i >> 7, sx = i & 127;
            Bs[kk][sx] = g_qkv2[(size_t)(b * 384 + 256 + cb * 16 + kk) * SPATIAL + s0 + sx];
        }
        __syncthreads();
#pragma unroll
        for (int kk = 0; kk < 16; ++kk) {
            u64 a2[4];
#pragma unroll
            for (int mp = 0; mp < 4; ++mp)
                a2[mp] = *(const u64*)&As[kk][tr * 8 + 2 * mp];
            const float* brow = &Bs[kk][tc * 8];
            float4 w0 = *(const float4*)brow;
            float4 w1 = *(const float4*)(brow + 4);
            u64 bb[8];
            bb[0] = pack2(w0.x, w0.x); bb[1] = pack2(w0.y, w0.y);
            bb[2] = pack2(w0.z, w0.z); bb[3] = pack2(w0.w, w0.w);
            bb[4] = pack2(w1.x, w1.x); bb[5] = pack2(w1.y, w1.y);
            bb[6] = pack2(w1.z, w1.z); bb[7] = pack2(w1.w, w1.w);
#pragma unroll
            for (int mp = 0; mp < 4; ++mp)
#pragma unroll
                for (int n = 0; n < 8; ++n)
                    acc2[mp][n] = fma2(a2[mp], bb[n], acc2[mp][n]);
        }
        __syncthreads();
    }

#pragma unroll
    for (int mp = 0; mp < 4; ++mp) {
        int oA = tr * 8 + 2 * mp;
        float b0 = pob[oA], b1 = pob[oA + 1];
        float* op0 = out + (size_t)(b * 128 + oA) * SPATIAL + s0 + tc * 8;
        float* op1 = op0 + SPATIAL;
#pragma unroll
        for (int n = 0; n < 8; ++n) {
            float2 v = unpack2(acc2[mp][n]);
            op0[n] = v.x + b0;
            op1[n] = v.y + b1;
        }
    }
}

// ---------------------------------------------------------------------------
extern "C" void kernel_launch(void* const* d_in, const int* in_sizes, int n_in,
                              void* d_out, int out_size) {
    const float* x     = (const float*)d_in[0];
    const float* qkv_r = (const float*)d_in[1];
    const float* qkv_i = (const float*)d_in[2];
    const float* qkv_j = (const float*)d_in[3];
    const float* qkv_k = (const float*)d_in[4];
    const float* qkv_b = (const float*)d_in[5];
    const float* dw_r  = (const float*)d_in[6];
    const float* dw_i  = (const float*)d_in[7];
    const float* dw_j  = (const float*)d_in[8];
    const float* dw_k  = (const float*)d_in[9];
    const float* dw_b  = (const float*)d_in[10];
    const float* po_r  = (const float*)d_in[11];
    const float* po_i  = (const float*)d_in[12];
    const float* po_j  = (const float*)d_in[13];
    const float* po_k  = (const float*)d_in[14];
    const float* po_b  = (const float*)d_in[15];
    const float* temp  = (const float*)d_in[16];
    float* out = (float*)d_out;

    // launches 1..5 (conv must be the 6th launch for ncu -s 5 -c 1)
    zero_scratch<<<34, 256>>>();
    expand_hamilton<<<192, 256>>>(qkv_r, qkv_i, qkv_j, qkv_k, 0, 96, 32, 1);
    expand_hamilton<<<5184, 256>>>(dw_r, dw_i, dw_j, dw_k, 1, 96, 96, 9);
    expand_hamilton<<<64, 256>>>(po_r, po_i, po_j, po_k, 2, 32, 32, 1);
    weff_o<<<384, 128>>>(qkv_b);

    // launch 6: dominant conv (profiled)
    conv_fused<<<dim3(128, 3, 2), 256>>>(x, dw_b);

    // attention tail
    norms_finish<<<2, 256>>>();
    attn_partial<<<dim3(16, 8), 256>>>();
    softmax_kernel<<<256, 32>>>(temp);
    make_M2<<<dim3(2, 4), 256>>>();
    final_gemm<<<dim3(128, 1, 2), 256>>>(po_b, out);
}

// round 5
// speedup vs baseline: 2.6701x; 2.5128x over previous
#include <cuda_runtime.h>
#include <cuda_bf16.h>
#include <cstdint>
#include <math.h>

// ---------------------------------------------------------------------------
// QAttention round 5: conv via warp-level mma.sync (HMMA bf16, hi/lo 3-pass).
// (tcgen05 is unavailable: harness ptxas targets sm_103 without the 'a' feature)
//   P1 prep_x: transpose x -> xt_hi/xt_lo [b][s][c] bf16 (+zero scratch)
//   P2 expand Hamilton blocks -> full weights
//   P3 weff_o: Weff = Wdw_tap @ Wqkv -> bf16 hi/lo [o][tap*128+c]; tb fold
//   P4 conv_mma: implicit-GEMM 3x3 conv on HMMA -> g_qkv2 fp32 (+sumsq)
//   P5.. attention tail (fp32, unchanged from round 3)
// ---------------------------------------------------------------------------

#define SPATIAL 16384
typedef unsigned long long u64;

// ------------------------- mma.sync helpers --------------------------------
__device__ __forceinline__ uint32_t smem_to_u32(const void* p) {
    uint32_t a;
    asm("{ .reg .u64 t; cvta.to.shared.u64 t, %1; cvt.u32.u64 %0, t; }"
        : "=r"(a) : "l"(p));
    return a;
}
__device__ __forceinline__ void ldsm4(uint32_t* r, uint32_t addr) {
    asm volatile("ldmatrix.sync.aligned.m8n8.x4.shared.b16 {%0,%1,%2,%3}, [%4];"
                 : "=r"(r[0]), "=r"(r[1]), "=r"(r[2]), "=r"(r[3]) : "r"(addr));
}
__device__ __forceinline__ void mma_bf16(float* d, const uint32_t* a,
                                         const uint32_t* b) {
    asm volatile(
        "mma.sync.aligned.m16n8k16.row.col.f32.bf16.bf16.f32 "
        "{%0,%1,%2,%3}, {%4,%5,%6,%7}, {%8,%9}, {%0,%1,%2,%3};"
        : "+f"(d[0]), "+f"(d[1]), "+f"(d[2]), "+f"(d[3])
        : "r"(a[0]), "r"(a[1]), "r"(a[2]), "r"(a[3]), "r"(b[0]), "r"(b[1]));
}
// swizzled smem address: tile rows of 128B (8 x 16B units), unit ^= row&7
__device__ __forceinline__ uint32_t sw_addr(uint32_t base, int row, int unit) {
    return base + row * 128 + (((unit) ^ (row & 7)) << 4);
}

// ------------------------- f32x2 helpers (final_gemm) ----------------------
__device__ __forceinline__ u64 pack2(float lo, float hi) {
    u64 r; asm("mov.b64 %0,{%1,%2};" : "=l"(r) : "f"(lo), "f"(hi)); return r;
}
__device__ __forceinline__ float2 unpack2(u64 v) {
    float2 f; asm("mov.b64 {%0,%1},%2;" : "=f"(f.x), "=f"(f.y) : "l"(v)); return f;
}
__device__ __forceinline__ u64 fma2(u64 a, u64 b, u64 c) {
    u64 d; asm("fma.rn.f32x2 %0,%1,%2,%3;" : "=l"(d) : "l"(a), "l"(b), "l"(c)); return d;
}

// ------------------------- device scratch ----------------------------------
__device__ float g_Wqkv[384 * 128];
__device__ float g_Wdw[384 * 384 * 9];
__device__ float g_Wpo[128 * 128];
__device__ __nv_bfloat16 g_WeffHi[384 * 1152];   // [o][tap*128+c]
__device__ __nv_bfloat16 g_WeffLo[384 * 1152];
__device__ float g_tb[384 * 9];
__device__ __nv_bfloat16 g_xt_hi[2 * SPATIAL * 128];  // [b][s][c]
__device__ __nv_bfloat16 g_xt_lo[2 * SPATIAL * 128];
__device__ float g_qkv2[2 * 384 * SPATIAL];
__device__ float g_attnP[2 * 4 * 32 * 32];
__device__ float g_attn[2 * 4 * 32 * 32];
__device__ float g_inv[2 * 2 * 128];
__device__ float g_ss[2 * 256];
__device__ float g_M2[2 * 128 * 128];

// ---------------------------------------------------------------------------
// P1: transpose x to [b][s][c] bf16 hi/lo; block(0,0) also zeros scratch.
// ---------------------------------------------------------------------------
__global__ void prep_x(const float* __restrict__ X) {
    __shared__ float t[128][33];
    int s0 = blockIdx.x * 32;
    int b  = blockIdx.y;
    int tid = threadIdx.x;

    if (blockIdx.x == 0 && b == 0) {
        for (int i = tid; i < 8192; i += 256) g_attnP[i] = 0.f;
        for (int i = tid; i < 512; i += 256) g_ss[i] = 0.f;
    }
    for (int i = tid; i < 4096; i += 256) {
        int c = i >> 5, s = i & 31;
        t[c][s] = X[((size_t)(b * 128 + c)) * SPATIAL + s0 + s];
    }
    __syncthreads();
    for (int i = tid; i < 4096; i += 256) {
        int s = i >> 7, c = i & 127;
        float v = t[c][s];
        __nv_bfloat16 hi = __float2bfloat16(v);
        float vlo = v - __bfloat162float(hi);
        size_t idx = ((size_t)b * SPATIAL + s0 + s) * 128 + c;
        g_xt_hi[idx] = hi;
        g_xt_lo[idx] = __float2bfloat16(vlo);
    }
}

// ---------------------------------------------------------------------------
// P2: Hamilton-product block expansion.
// ---------------------------------------------------------------------------
__global__ void expand_hamilton(const float* __restrict__ r,
                                const float* __restrict__ i_,
                                const float* __restrict__ j_,
                                const float* __restrict__ k_,
                                int dest, int O4, int C4, int T) {
    int idx = blockIdx.x * blockDim.x + threadIdx.x;
    int total = 16 * O4 * C4 * T;
    if (idx >= total) return;

    int tap = idx % T;
    int rem = idx / T;
    int C = 4 * C4;
    int c = rem % C;
    int o = rem / C;
    int br = o / O4, oo = o % O4;
    int bc = c / C4, cc = c % C4;

    const int   src[16] = {0,1,2,3, 1,0,3,2, 2,3,0,1, 3,2,1,0};
    const float sgn[16] = {1.f,-1.f,-1.f,-1.f, 1.f,1.f,-1.f,1.f,
                           1.f,1.f,1.f,-1.f,  1.f,-1.f,1.f,1.f};
    const float* comp[4] = {r, i_, j_, k_};

    float v = sgn[br * 4 + bc] * comp[src[br * 4 + bc]][(oo * C4 + cc) * T + tap];
    if (dest == 0) g_Wqkv[idx] = v;
    else if (dest == 1) g_Wdw[idx] = v;
    else g_Wpo[idx] = v;
}

// ---------------------------------------------------------------------------
// P3: Weff per output row -> bf16 hi/lo at [o][tap*128+c]; tb fold.
// ---------------------------------------------------------------------------
__global__ __launch_bounds__(128)
void weff_o(const float* __restrict__ qkv_b) {
    int o = blockIdx.x;
    int c = threadIdx.x;

    __shared__ float wdw_s[288 + 8];
    __shared__ float wq_s[32 * 128];
    __shared__ float qb_s[384];

    for (int m = c; m < 384; m += 128) qb_s[m] = qkv_b[m];

    float acc[9], tbp[9];
#pragma unroll
    for (int t = 0; t < 9; ++t) { acc[t] = 0.f; tbp[t] = 0.f; }

    const float* wdw_row = g_Wdw + (size_t)o * 3456;

    for (int cb = 0; cb < 12; ++cb) {
        __syncthreads();
        for (int i = c; i < 288; i += 128)
            wdw_s[i] = wdw_row[cb * 288 + i];
        for (int i = c; i < 4096; i += 128) {
            int m = i >> 7, col = i & 127;
            wq_s[m * 128 + col] = g_Wqkv[(cb * 32 + m) * 128 + col];
        }
        __syncthreads();
#pragma unroll 4
        for (int m = 0; m < 32; ++m) {
            float wq = wq_s[m * 128 + c];
#pragma unroll
            for (int t = 0; t < 9; ++t)
                acc[t] = fmaf(wdw_s[m * 9 + t], wq, acc[t]);
        }
        if (c < 32) {
            float qb = qb_s[cb * 32 + c];
#pragma unroll
            for (int t = 0; t < 9; ++t)
                tbp[t] = fmaf(wdw_s[c * 9 + t], qb, tbp[t]);
        }
    }

#pragma unroll
    for (int t = 0; t < 9; ++t) {
        float a = acc[t];
        __nv_bfloat16 hi = __float2bfloat16(a);
        g_WeffHi[(size_t)o * 1152 + t * 128 + c] = hi;
        g_WeffLo[(size_t)o * 1152 + t * 128 + c] =
            __float2bfloat16(a - __bfloat162float(hi));
    }

    if (c < 32) {
#pragma unroll
        for (int t = 0; t < 9; ++t) {
            float v = tbp[t];
#pragma unroll
            for (int off = 16; off; off >>= 1)
                v += __shfl_xor_sync(0xffffffffu, v, off);
            if (c == 0) g_tb[o * 9 + t] = v;
        }
    }
}

// ---------------------------------------------------------------------------
// P4: conv via mma.sync. CTA = M128 (chans) x N128 (one image row y).
// 8 warps 2(M)x4(N); warp tile 64x32; m16n8k16 bf16, fp32 accum.
// K: 9 taps x 2 chunks of 64 ch = 18 iterations x 4 k16-steps; hi/lo 3-pass.
// smem: Ahi/Alo/Bhi/Blo 16KB each, XOR-swizzled (128B rows, 8 units).
// ---------------------------------------------------------------------------
#define SM_AHI 0
#define SM_ALO (16 * 1024)
#define SM_BHI (32 * 1024)
#define SM_BLO (48 * 1024)
#define CONV_SMEM (64 * 1024)

__global__ __launch_bounds__(256)
void conv_mma(const float* __restrict__ dwb) {
    extern __shared__ char smem[];
    uint32_t sbase = smem_to_u32(smem);
    int tid = threadIdx.x, wid = tid >> 5, lane = tid & 31;
    int y  = blockIdx.x;          // image row
    int o0 = blockIdx.y * 128;    // output-channel tile
    int b  = blockIdx.z;

    int warpM = wid >> 2;         // 0..1 -> 64 chans
    int warpN = wid & 3;          // 0..3 -> 32 pixels
    int lr = lane >> 3;           // lane%8 row within ldmatrix
    int lm = lane >> 3;           // matrix id = lane/8
    int r8 = lane & 7;

    float acc[4][4][4];
#pragma unroll
    for (int mt = 0; mt < 4; ++mt)
#pragma unroll
        for (int nt = 0; nt < 4; ++nt)
#pragma unroll
            for (int q = 0; q < 4; ++q) acc[mt][nt][q] = 0.f;

    uint32_t sAhi = sbase + SM_AHI, sAlo = sbase + SM_ALO;
    uint32_t sBhi = sbase + SM_BHI, sBlo = sbase + SM_BLO;

    for (int it = 0; it < 18; ++it) {
        int tap = it >> 1;
        int ch  = (it & 1) * 64;
        int dy = tap / 3 - 1, dx = tap % 3 - 1;

        if (it) __syncthreads();   // previous compute done before refill

        // A fill: [128 o][64 k] hi+lo = 2048 uint4
        for (int i = tid; i < 2048; i += 256) {
            int half = i >> 10, row = (i >> 3) & 127, u = i & 7;
            const __nv_bfloat16* src =
                (half ? g_WeffLo : g_WeffHi) +
                (size_t)(o0 + row) * 1152 + tap * 128 + ch + u * 8;
            uint4 v = *(const uint4*)src;
            *(uint4*)(smem + (half ? SM_ALO : SM_AHI) + row * 128 +
                      ((u ^ (row & 7)) << 4)) = v;
        }
        // B fill: [128 x][64 k] hi+lo, gathered with (dy,dx), zero halo
        {
            int yy = y + dy;
            bool yok = (unsigned)yy < 128u;
            for (int i = tid; i < 2048; i += 256) {
                int half = i >> 10, row = (i >> 3) & 127, u = i & 7;
                int xx = row + dx;
                uint4 v = make_uint4(0u, 0u, 0u, 0u);
                if (yok && (unsigned)xx < 128u) {
                    const __nv_bfloat16* src =
                        (half ? g_xt_lo : g_xt_hi) +
                        ((size_t)b * SPATIAL + yy * 128 + xx) * 128 + ch + u * 8;
                    v = *(const uint4*)src;
                }
                *(uint4*)(smem + (half ? SM_BLO : SM_BHI) + row * 128 +
                          ((u ^ (row & 7)) << 4)) = v;
            }
        }
        __syncthreads();

#pragma unroll
        for (int ks = 0; ks < 4; ++ks) {
            // B frags: 2x ldsm4 per half -> 4 n-tiles (2 regs each)
            uint32_t bhi[8], blo[8];
#pragma unroll
            for (int p = 0; p < 2; ++p) {
                int rowB = warpN * 32 + p * 16 + ((lm >> 1) << 3) + r8;
                int unitB = ks * 2 + (lm & 1);
                ldsm4(&bhi[p * 4], sw_addr(sBhi, rowB, unitB));
                ldsm4(&blo[p * 4], sw_addr(sBlo, rowB, unitB));
            }
#pragma unroll
            for (int mt = 0; mt < 4; ++mt) {
                int rowA = warpM * 64 + mt * 16 + ((lm & 1) << 3) + r8;
                int unitA = ks * 2 + (lm >> 1);
                uint32_t ahi[4], alo[4];
                ldsm4(ahi, sw_addr(sAhi, rowA, unitA));
                ldsm4(alo, sw_addr(sAlo, rowA, unitA));
#pragma unroll
                for (int nt = 0; nt < 4; ++nt) {
                    mma_bf16(acc[mt][nt], ahi, &bhi[nt * 2]);
                    mma_bf16(acc[mt][nt], ahi, &blo[nt * 2]);
                    mma_bf16(acc[mt][nt], alo, &bhi[nt * 2]);
                }
            }
        }
    }
    __syncthreads();

    // bias triple per local o into smem (reuse tile A region)
    float* bias_s = (float*)smem;   // [128][3]
    if (tid < 128) {
        int o = o0 + tid;
        const float* t = &g_tb[o * 9];
        float f0 = (y >= 1) ? 1.f : 0.f;
        float f2 = (y <= 126) ? 1.f : 0.f;
        bias_s[tid * 3 + 0] = dwb[o] + f0 * t[1] + t[4] + f2 * t[7];
        bias_s[tid * 3 + 1] = f0 * t[0] + t[3] + f2 * t[6];
        bias_s[tid * 3 + 2] = f0 * t[2] + t[5] + f2 * t[8];
    }
    __syncthreads();

    // epilogue: D frag lane mapping: c0,c1 -> row lane/4, cols 2*(lane%4)+{0,1};
    // c2,c3 -> row lane/4+8.
    int rr = lane >> 2;
    int q2 = (lane & 3) * 2;
    bool doss = (o0 < 256);
#pragma unroll
    for (int mt = 0; mt < 4; ++mt) {
#pragma unroll
        for (int half = 0; half < 2; ++half) {
            int o_loc = warpM * 64 + mt * 16 + rr + half * 8;
            int o = o0 + o_loc;
            float base = bias_s[o_loc * 3 + 0];
            float rs0  = bias_s[o_loc * 3 + 1];
            float rs2  = bias_s[o_loc * 3 + 2];
            float ss = 0.f;
            float* dst = g_qkv2 + (size_t)(b * 384 + o) * SPATIAL + y * 128;
#pragma unroll
            for (int nt = 0; nt < 4; ++nt) {
                int x = warpN * 32 + nt * 8 + q2;      // even, 0..126
                float v0 = acc[mt][nt][half * 2 + 0] + base + rs2;
                if (x >= 1) v0 += rs0;
                float v1 = acc[mt][nt][half * 2 + 1] + base + rs0;
                if (x + 1 <= 126) v1 += rs2;
                *(float2*)(dst + x) = make_float2(v0, v1);
                ss = fmaf(v0, v0, ss);
                ss = fmaf(v1, v1, ss);
            }
            // reduce over the 4 lanes sharing this o (same lane/4 group)
            ss += __shfl_xor_sync(0xffffffffu, ss, 1);
            ss += __shfl_xor_sync(0xffffffffu, ss, 2);
            if (doss && (lane & 3) == 0)
                atomicAdd(&g_ss[b * 256 + o], ss);
        }
    }
}

// ---------------------------------------------------------------------------
// P5: finish inverse norms.
// ---------------------------------------------------------------------------
__global__ void norms_finish() {
    int r = blockIdx.x * 256 + threadIdx.x;
    if (r >= 512) return;
    int qk = r >> 8;
    int b  = (r >> 7) & 1;
    int ch = r & 127;
    float ss = g_ss[b * 256 + qk * 128 + ch];
    g_inv[r] = 1.f / fmaxf(sqrtf(ss), 1e-12f);
}

// ---------------------------------------------------------------------------
// P6: attn partial sums (K-split + atomics).
// ---------------------------------------------------------------------------
__global__ void attn_partial() {
    int slice = blockIdx.x;
    int bh = blockIdx.y;
    int b = bh >> 2, h = bh & 3;
    const float* qb = g_qkv2 + (size_t)(b * 384 + h * 32) * SPATIAL;
    const float* kb = g_qkv2 + (size_t)(b * 384 + 128 + h * 32) * SPATIAL;

    __shared__ float qs[32][65], ks[32][65];
    int tid = threadIdx.x;
    int c = tid >> 3;
    int d0 = (tid & 7) * 4;
    float acc[4] = {0.f, 0.f, 0.f, 0.f};

    for (int sub = 0; sub < 16; ++sub) {
        int s0 = slice * 1024 + sub * 64;
        for (int i = tid; i < 2048; i += 256) {
            int cc = i >> 6, kk = i & 63;
            qs[cc][kk] = qb[(size_t)cc * SPATIAL + s0 + kk];
            ks[cc][kk] = kb[(size_t)cc * SPATIAL + s0 + kk];
        }
        __syncthreads();
#pragma unroll 8
        for (int kk = 0; kk < 64; ++kk) {
            float qv = qs[c][kk];
#pragma unroll
            for (int j = 0; j < 4; ++j)
                acc[j] = fmaf(qv, ks[d0 + j][kk], acc[j]);
        }
        __syncthreads();
    }
#pragma unroll
    for (int j = 0; j < 4; ++j)
        atomicAdd(&g_attnP[(bh * 32 + c) * 32 + d0 + j], acc[j]);
}

// ---------------------------------------------------------------------------
// P7: softmax with inv-norms and temperature fused in.
// ---------------------------------------------------------------------------
__global__ void softmax_kernel(const float* __restrict__ temp) {
    int row = blockIdx.x;
    int bh = row >> 5, c = row & 31;
    int b = bh >> 2, h = bh & 3;
    int d = threadIdx.x;

    float invq = g_inv[b * 128 + h * 32 + c];
    float invk = g_inv[256 + b * 128 + h * 32 + d];
    float v = g_attnP[row * 32 + d] * invq * invk * temp[h];

    float mx = v;
#pragma unroll
    for (int off = 16; off; off >>= 1)
        mx = fmaxf(mx, __shfl_xor_sync(0xffffffffu, mx, off));
    float e = expf(v - mx);
    float s = e;
#pragma unroll
    for (int off = 16; off; off >>= 1)
        s += __shfl_xor_sync(0xffffffffu, s, off);
    g_attn[row * 32 + d] = e / s;
}

// ---------------------------------------------------------------------------
// P8: M2[b][o][h*32+d] = sum_c Wpo[o][h*32+c] * attn[bh][c][d]
// ---------------------------------------------------------------------------
__global__ void make_M2() {
    int b = blockIdx.x, h = blockIdx.y;
    int bh = b * 4 + h;
    int tid = threadIdx.x;

    __shared__ float A[32][33];
    __shared__ float W[128][33];

    for (int i = tid; i < 1024; i += 256) {
        int c = i >> 5, d = i & 31;
        A[c][d] = g_attn[(bh * 32 + c) * 32 + d];
    }
    for (int i = tid; i < 4096; i += 256) {
        int o = i >> 5, c = i & 31;
        W[o][c] = g_Wpo[o * 128 + h * 32 + c];
    }
    __syncthreads();

    int o = tid >> 1;
    int d0 = (tid & 1) * 16;
#pragma unroll
    for (int dd = 0; dd < 16; ++dd) {
        int d = d0 + dd;
        float s = 0.f;
#pragma unroll
        for (int c = 0; c < 32; ++c)
            s = fmaf(W[o][c], A[c][d], s);
        g_M2[b * 16384 + o * 128 + h * 32 + d] = s;
    }
}

// ---------------------------------------------------------------------------
// P9: out[b][o][s] = sum_dg M2[b][o][dg] * v[b][dg][s] + po_b[o]  (fp32x2)
// ---------------------------------------------------------------------------
__global__ __launch_bounds__(256)
void final_gemm(const float* __restrict__ pob, float* __restrict__ out) {
    int s0 = blockIdx.x * 128;
    int b  = blockIdx.z;
    int tid = threadIdx.x;
    int tr = tid >> 4, tc = tid & 15;

    __shared__ float As[16][128];
    __shared__ float Bs[16][132];

    u64 acc2[4][8];
#pragma unroll
    for (int mp = 0; mp < 4; ++mp)
#pragma unroll
        for (int n = 0; n < 8; ++n) acc2[mp][n] = 0ull;

    for (int cb = 0; cb < 8; ++cb) {
        for (int i = tid; i < 2048; i += 256) {
            int o = i >> 4, kk = i & 15;
            As[kk][o] = g_M2[b * 16384 + o * 128 + cb * 16 + kk];
        }
        for (int i = tid; i < 2048; i += 256) {
            int kk = i >> 7, sx = i & 127;
            Bs[kk][sx] = g_qkv2[(size_t)(b * 384 + 256 + cb * 16 + kk) * SPATIAL + s0 + sx];
        }
        __syncthreads();
#pragma unroll
        for (int kk = 0; kk < 16; ++kk) {
            u64 a2[4];
#pragma unroll
            for (int mp = 0; mp < 4; ++mp)
                a2[mp] = *(const u64*)&As[kk][tr * 8 + 2 * mp];
            const float* brow = &Bs[kk][tc * 8];
            float4 w0 = *(const float4*)brow;
            float4 w1 = *(const float4*)(brow + 4);
            u64 bb[8];
            bb[0] = pack2(w0.x, w0.x); bb[1] = pack2(w0.y, w0.y);
            bb[2] = pack2(w0.z, w0.z); bb[3] = pack2(w0.w, w0.w);
            bb[4] = pack2(w1.x, w1.x); bb[5] = pack2(w1.y, w1.y);
            bb[6] = pack2(w1.z, w1.z); bb[7] = pack2(w1.w, w1.w);
#pragma unroll
            for (int mp = 0; mp < 4; ++mp)
#pragma unroll
                for (int n = 0; n < 8; ++n)
                    acc2[mp][n] = fma2(a2[mp], bb[n], acc2[mp][n]);
        }
        __syncthreads();
    }

#pragma unroll
    for (int mp = 0; mp < 4; ++mp) {
        int oA = tr * 8 + 2 * mp;
        float b0 = pob[oA], b1 = pob[oA + 1];
        float* op0 = out + (size_t)(b * 128 + oA) * SPATIAL + s0 + tc * 8;
        float* op1 = op0 + SPATIAL;
#pragma unroll
        for (int n = 0; n < 8; ++n) {
            float2 v = unpack2(acc2[mp][n]);
            op0[n] = v.x + b0;
            op1[n] = v.y + b1;
        }
    }
}

// ---------------------------------------------------------------------------
extern "C" void kernel_launch(void* const* d_in, const int* in_sizes, int n_in,
                              void* d_out, int out_size) {
    const float* x     = (const float*)d_in[0];
    const float* qkv_r = (const float*)d_in[1];
    const float* qkv_i = (const float*)d_in[2];
    const float* qkv_j = (const float*)d_in[3];
    const float* qkv_k = (const float*)d_in[4];
    const float* qkv_b = (const float*)d_in[5];
    const float* dw_r  = (const float*)d_in[6];
    const float* dw_i  = (const float*)d_in[7];
    const float* dw_j  = (const float*)d_in[8];
    const float* dw_k  = (const float*)d_in[9];
    const float* dw_b  = (const float*)d_in[10];
    const float* po_r  = (const float*)d_in[11];
    const float* po_i  = (const float*)d_in[12];
    const float* po_j  = (const float*)d_in[13];
    const float* po_k  = (const float*)d_in[14];
    const float* po_b  = (const float*)d_in[15];
    const float* temp  = (const float*)d_in[16];
    float* out = (float*)d_out;

    cudaFuncSetAttribute(conv_mma, cudaFuncAttributeMaxDynamicSharedMemorySize,
                         CONV_SMEM);

    // launches 1..5 (conv is the 6th for ncu -s 5 -c 1)
    prep_x<<<dim3(512, 2), 256>>>(x);
    expand_hamilton<<<192, 256>>>(qkv_r, qkv_i, qkv_j, qkv_k, 0, 96, 32, 1);
    expand_hamilton<<<5184, 256>>>(dw_r, dw_i, dw_j, dw_k, 1, 96, 96, 9);
    expand_hamilton<<<64, 256>>>(po_r, po_i, po_j, po_k, 2, 32, 32, 1);
    weff_o<<<384, 128>>>(qkv_b);

    // launch 6: HMMA conv
    conv_mma<<<dim3(128, 3, 2), 256, CONV_SMEM>>>(dw_b);

    // attention tail
    norms_finish<<<2, 256>>>();
    attn_partial<<<dim3(16, 8), 256>>>();
    softmax_kernel<<<256, 32>>>(temp);
    make_M2<<<dim3(2, 4), 256>>>();
    final_gemm<<<dim3(128, 1, 2), 256>>>(po_b, out);
}